// round 16
// baseline (speedup 1.0000x reference)
#include <cuda_runtime.h>
#include <cuda_fp16.h>
#include <cstdint>

#define Bb   2
#define Ls   2048
#define Hh   16
#define Dd   256
#define HD   4096   // H*D
#define KD   2048   // HKV*D
#define HIDd 2048
#define NB   8
#define BLK  256
#define NQKV 8192   // HD + KD + KD

// ---------------- scratch (static device memory; no allocs) ----------------
static __device__ __align__(128) float g_qkvpre[Bb * Ls * NQKV];
static __device__ __align__(128) float g_kf  [Bb * Ls * KD];
static __device__ __align__(128) float g_kv  [Bb * Hh * NB * Dd * Dd];
static __device__ __align__(128) float g_o   [Bb * Ls * HD];
static __device__ __align__(128) float g_kT  [16 * Dd * Ls];

static __device__ __align__(128) __half g_xh   [Bb * Ls * HIDd];
static __device__ __align__(128) __half g_xl   [Bb * Ls * HIDd];
static __device__ __align__(128) __half g_wqkvh[NQKV * HIDd];
static __device__ __align__(128) __half g_woh  [HIDd * HD];
static __device__ __align__(128) __half g_oh   [Bb * Ls * HD];
static __device__ __align__(128) __half g_ol   [Bb * Ls * HD];
static __device__ __align__(128) __half g_qh   [Bb * Ls * HD];
static __device__ __align__(128) __half g_ql   [Bb * Ls * HD];
static __device__ __align__(128) __half g_kh   [Bb * Ls * KD];
static __device__ __align__(128) __half g_vTh  [16 * Dd * Ls];
static __device__ __align__(128) __half g_vTl  [16 * Dd * Ls];
static __device__ __align__(128) __half g_kvTh [Bb * Hh * NB * Dd * Dd];
static __device__ __align__(128) __half g_sch  [Bb * Hh * NB * BLK * BLK];
static __device__ __align__(128) __half g_scl  [Bb * Hh * NB * BLK * BLK];

// =======================================================================
// helpers
// =======================================================================
__device__ __forceinline__ uint32_t smem_u32(const void* p) {
    uint32_t a;
    asm("{ .reg .u64 t; cvta.to.shared.u64 t, %1; cvt.u32.u64 %0, t; }" : "=r"(a) : "l"(p));
    return a;
}
__device__ __forceinline__ void split2h(float x0, float x1, uint32_t& hi, uint32_t& lo) {
    __half2 h = __floats2half2_rn(x0, x1);
    float r0 = x0 - __half2float(__low2half(h));
    float r1 = x1 - __half2float(__high2half(h));
    __half2 l = __floats2half2_rn(r0, r1);
    hi = *reinterpret_cast<uint32_t*>(&h);
    lo = *reinterpret_cast<uint32_t*>(&l);
}
__device__ __forceinline__ uint32_t round2h(float x0, float x1) {
    __half2 h = __floats2half2_rn(x0, x1);
    return *reinterpret_cast<uint32_t*>(&h);
}
#define CPA16(dst, src) asm volatile("cp.async.cg.shared.global [%0], [%1], 16;" :: "r"(dst), "l"(src))
#define CPCOMMIT()      asm volatile("cp.async.commit_group;" ::: "memory")
#define CPWAIT1()       asm volatile("cp.async.wait_group 1;" ::: "memory")
__device__ __forceinline__ void ldsm4(uint32_t a, uint32_t* r) {
    asm volatile("ldmatrix.sync.aligned.m8n8.x4.shared.b16 {%0,%1,%2,%3}, [%4];"
                 : "=r"(r[0]), "=r"(r[1]), "=r"(r[2]), "=r"(r[3]) : "r"(a));
}
__device__ __forceinline__ void mma16816(float* d, const uint32_t* a, const uint32_t* b) {
    asm volatile("mma.sync.aligned.m16n8k16.row.col.f32.f16.f16.f32 "
                 "{%0,%1,%2,%3}, {%4,%5,%6,%7}, {%8,%9}, {%0,%1,%2,%3};"
                 : "+f"(d[0]), "+f"(d[1]), "+f"(d[2]), "+f"(d[3])
                 : "r"(a[0]), "r"(a[1]), "r"(a[2]), "r"(a[3]), "r"(b[0]), "r"(b[1]));
}

// ---------- 128x128-tile layout (attention kernels): A hi/lo + B hi ----------
#define SA_H 0
#define SA_L 16384
#define SB_H 32768
#define STAGE_B 49152
#define HG_SMEM (2 * STAGE_B)

__device__ __forceinline__ void stage_mma(uint32_t sb, float acc[4][4][4],
                                          int wm, int wn, int lane)
{
    const int rA = lane & 15, kA = lane >> 4;
    const int rB = (lane & 7) | ((lane & 16) >> 1), kB = (lane >> 3) & 1;
    const int e = lane & 7;
    const uint32_t baseA = sb + (uint32_t)((wm + rA) * 128);
    const uint32_t baseB = sb + (uint32_t)((wn + rB) * 128);
#pragma unroll
    for (int kk = 0; kk < 4; kk++) {
        const uint32_t cA = (uint32_t)(((2 * kk + kA) ^ e) << 4);
        const uint32_t cB = (uint32_t)(((2 * kk + kB) ^ e) << 4);
        uint32_t ah[4][4], al[4][4], bh[2][4];
#pragma unroll
        for (int mi = 0; mi < 4; mi++) {
            ldsm4(baseA + SA_H + mi * 2048 + cA, ah[mi]);
            ldsm4(baseA + SA_L + mi * 2048 + cA, al[mi]);
        }
#pragma unroll
        for (int nj = 0; nj < 2; nj++)
            ldsm4(baseB + SB_H + nj * 2048 + cB, bh[nj]);
#pragma unroll
        for (int mi = 0; mi < 4; mi++)
#pragma unroll
            for (int ni = 0; ni < 4; ni++) {
                const uint32_t* bph = &bh[ni >> 1][(ni & 1) * 2];
                mma16816(acc[mi][ni], ah[mi], bph);
                mma16816(acc[mi][ni], al[mi], bph);
            }
    }
}

__device__ __forceinline__ void fill_pair(uint32_t sb_h, uint32_t sb_l,
                                          const __half* gh, const __half* gl,
                                          size_t stride, int fr, int fc)
{
#pragma unroll
    for (int i = 0; i < 4; i++) {
        int r = fr + 32 * i;
        uint32_t doff = (uint32_t)(r * 128 + ((fc ^ (r & 7)) << 4));
        size_t so = (size_t)r * stride + fc * 8;
        CPA16(sb_h + doff, gh + so);
        CPA16(sb_l + doff, gl + so);
    }
}

__device__ __forceinline__ void fill_one(uint32_t sb_h, const __half* gh,
                                         size_t stride, int fr, int fc)
{
#pragma unroll
    for (int i = 0; i < 4; i++) {
        int r = fr + 32 * i;
        uint32_t doff = (uint32_t)(r * 128 + ((fc ^ (r & 7)) << 4));
        CPA16(sb_h + doff, gh + (size_t)r * stride + fc * 8);
    }
}

__device__ __forceinline__ void fill_f32_decay(char* smh, const float* g, size_t stride,
                                               int fr, int fc, float kd0, float ek)
{
    float kd[8];
    kd[0] = kd0;
#pragma unroll
    for (int j = 1; j < 8; j++) kd[j] = kd[j - 1] * ek;
#pragma unroll
    for (int i = 0; i < 4; i++) {
        int r = fr + 32 * i;
        uint32_t doff = (uint32_t)(r * 128 + ((fc ^ (r & 7)) << 4));
        const float* sp = g + (size_t)r * stride + fc * 8;
        float4 u = *(const float4*)sp;
        float4 w = *(const float4*)(sp + 4);
        uint4 hi;
        hi.x = round2h(u.x * kd[0], u.y * kd[1]);
        hi.y = round2h(u.z * kd[2], u.w * kd[3]);
        hi.z = round2h(w.x * kd[4], w.y * kd[5]);
        hi.w = round2h(w.z * kd[6], w.w * kd[7]);
        *(uint4*)(smh + doff) = hi;
    }
}

// manual A staging: reconstruct q from hi/lo, scale by qdec(row), re-split
__device__ __forceinline__ void fill_q_qdec(char* smh, char* sml,
                                            const __half* gh, const __half* gl,
                                            size_t stride, int fr, int fc,
                                            float s, int mbase)
{
#pragma unroll
    for (int i = 0; i < 4; i++) {
        int r = fr + 32 * i;
        uint32_t doff = (uint32_t)(r * 128 + ((fc ^ (r & 7)) << 4));
        const float qd = expf(-s * (float)(mbase + r + 1));
        uint4 hv = *(const uint4*)(gh + (size_t)r * stride + fc * 8);
        uint4 lv = *(const uint4*)(gl + (size_t)r * stride + fc * 8);
        uint4 oh, ol;
        const uint32_t* hp = &hv.x;
        const uint32_t* lp = &lv.x;
        uint32_t* op = &oh.x;
        uint32_t* op2 = &ol.x;
#pragma unroll
        for (int j = 0; j < 4; j++) {
            __half2 h2 = *reinterpret_cast<const __half2*>(&hp[j]);
            __half2 l2 = *reinterpret_cast<const __half2*>(&lp[j]);
            float v0 = (__half2float(__low2half(h2)) + __half2float(__low2half(l2))) * qd;
            float v1 = (__half2float(__high2half(h2)) + __half2float(__high2half(l2))) * qd;
            split2h(v0, v1, op[j], op2[j]);
        }
        *(uint4*)(smh + doff) = oh;
        *(uint4*)(sml + doff) = ol;
    }
}

// =======================================================================
// hgemm2: 128(M) x 256(N), BK=64, 2-stage; C row stride = ldc
// =======================================================================
#define G2_SA_H 0
#define G2_SA_L 16384
#define G2_SB_H 32768
#define G2_STAGE 65536
#define G2_SMEM (2 * G2_STAGE)

__global__ __launch_bounds__(256, 1) void hgemm2(const __half* __restrict__ Ah,
                                                 const __half* __restrict__ Al,
                                                 const __half* __restrict__ Bh,
                                                 float* __restrict__ C,
                                                 int M, int K, int ldc)
{
    extern __shared__ char sm[];
    const uint32_t sbase = smem_u32(sm);
    const int tid = threadIdx.x, wid = tid >> 5, lane = tid & 31;
    const int m0 = blockIdx.y * 128, n0 = blockIdx.x * 256;
    const int wm = (wid & 1) * 64, wn = (wid >> 1) * 64;
    const int t4 = lane & 3, tq = lane >> 2;
    const int fr = tid >> 3, fc = tid & 7;

    const int rA = lane & 15, kA = lane >> 4;
    const int rB = (lane & 7) | ((lane & 16) >> 1), kB = (lane >> 3) & 1;
    const int e = lane & 7;

    float acc[4][8][4];
#pragma unroll
    for (int a = 0; a < 4; a++)
#pragma unroll
        for (int b = 0; b < 8; b++)
#pragma unroll
            for (int c = 0; c < 4; c++) acc[a][b][c] = 0.f;

#define FILL2(s, buf) do {                                                                \
    const uint32_t sb = sbase + (buf) * G2_STAGE;                                         \
    const int k0 = (s) * 64;                                                              \
    _Pragma("unroll")                                                                     \
    for (int i = 0; i < 4; i++) {                                                         \
        int r = fr + 32 * i;                                                              \
        uint32_t doff = (uint32_t)(r * 128 + ((fc ^ (r & 7)) << 4));                      \
        size_t so = (size_t)(m0 + r) * K + k0 + fc * 8;                                   \
        CPA16(sb + G2_SA_H + doff, Ah + so);                                              \
        CPA16(sb + G2_SA_L + doff, Al + so);                                              \
    }                                                                                     \
    _Pragma("unroll")                                                                     \
    for (int i = 0; i < 8; i++) {                                                         \
        int r = fr + 32 * i;                                                              \
        uint32_t doff = (uint32_t)(r * 128 + ((fc ^ (r & 7)) << 4));                      \
        CPA16(sb + G2_SB_H + doff, Bh + (size_t)(n0 + r) * K + k0 + fc * 8);              \
    }                                                                                     \
} while (0)

    const int S = K / 64;
    FILL2(0, 0); CPCOMMIT();
    FILL2(1, 1); CPCOMMIT();

    for (int s = 0; s < S; s++) {
        CPWAIT1();
        __syncthreads();
        const uint32_t sb = sbase + (s & 1) * G2_STAGE;
        const uint32_t baseA = sb + (uint32_t)((wm + rA) * 128);
        const uint32_t baseB = sb + (uint32_t)((wn + rB) * 128);
#pragma unroll
        for (int kk = 0; kk < 4; kk++) {
            const uint32_t cA = (uint32_t)(((2 * kk + kA) ^ e) << 4);
            const uint32_t cB = (uint32_t)(((2 * kk + kB) ^ e) << 4);
            uint32_t ah[4][4], al[4][4], bh[4][4];
#pragma unroll
            for (int mi = 0; mi < 4; mi++) {
                ldsm4(baseA + G2_SA_H + mi * 2048 + cA, ah[mi]);
                ldsm4(baseA + G2_SA_L + mi * 2048 + cA, al[mi]);
            }
#pragma unroll
            for (int nj = 0; nj < 4; nj++)
                ldsm4(baseB + G2_SB_H + nj * 2048 + cB, bh[nj]);
#pragma unroll
            for (int mi = 0; mi < 4; mi++)
#pragma unroll
                for (int ni = 0; ni < 8; ni++) {
                    const uint32_t* bph = &bh[ni >> 1][(ni & 1) * 2];
                    mma16816(acc[mi][ni], ah[mi], bph);
                    mma16816(acc[mi][ni], al[mi], bph);
                }
        }
        __syncthreads();
        if (s + 2 < S) FILL2(s + 2, s & 1);
        CPCOMMIT();
    }
#undef FILL2

#pragma unroll
    for (int mi = 0; mi < 4; mi++) {
        const int m = m0 + wm + mi * 16 + tq;
#pragma unroll
        for (int ni = 0; ni < 8; ni++) {
            const int n = n0 + wn + ni * 8 + t4 * 2;
            *(float2*)(C + (size_t)m * ldc + n)       = make_float2(acc[mi][ni][0], acc[mi][ni][1]);
            *(float2*)(C + (size_t)(m + 8) * ldc + n) = make_float2(acc[mi][ni][2], acc[mi][ni][3]);
        }
    }
}

// =======================================================================
// convert kernels
// =======================================================================
__global__ __launch_bounds__(256) void convsplit(const float* __restrict__ in,
                                                 __half* __restrict__ hi,
                                                 __half* __restrict__ lo, int n4)
{
    int i = blockIdx.x * 256 + threadIdx.x;
    if (i >= n4) return;
    float4 v = ((const float4*)in)[i];
    uint2 h, l;
    split2h(v.x, v.y, h.x, l.x);
    split2h(v.z, v.w, h.y, l.y);
    ((uint2*)hi)[i] = h;
    ((uint2*)lo)[i] = l;
}

__global__ __launch_bounds__(256) void tsplit(const float* __restrict__ W,
                                              __half* __restrict__ th,
                                              int Kd, int Nd)
{
    __shared__ float t[32][33];
    const int bxn = blockIdx.x * 32;
    const int byk = blockIdx.y * 32;
    const int x = threadIdx.x & 31, y = threadIdx.x >> 5;
#pragma unroll
    for (int j = 0; j < 4; j++)
        t[y + 8 * j][x] = W[(size_t)(byk + y + 8 * j) * Nd + bxn + x];
    __syncthreads();
    const int n = bxn + x;
    uint2 h;
    h.x = round2h(t[y * 4 + 0][x], t[y * 4 + 1][x]);
    h.y = round2h(t[y * 4 + 2][x], t[y * 4 + 3][x]);
    ((uint2*)th)[((size_t)n * Kd + byk + y * 4) >> 2] = h;
}

__global__ __launch_bounds__(256) void trans_f32(const float* __restrict__ in,
                                                 float* __restrict__ out)
{
    __shared__ float t[32][33];
    const int bk = blockIdx.z;
    const int b = bk >> 3, hk = bk & 7;
    const int l0 = blockIdx.x * 32, d0 = blockIdx.y * 32;
    const int x = threadIdx.x & 31, y = threadIdx.x >> 5;
#pragma unroll
    for (int j = 0; j < 4; j++)
        t[y + 8 * j][x] = in[(size_t)(b * Ls + l0 + y + 8 * j) * KD + hk * Dd + d0 + x];
    __syncthreads();
#pragma unroll
    for (int j = 0; j < 4; j++) {
        int d = d0 + y + 8 * j;
        out[((size_t)bk * Dd + d) * Ls + l0 + x] = t[x][y + 8 * j];
    }
}

__global__ __launch_bounds__(256) void trans_split(const float* __restrict__ in,
                                                   int instride, int colbase,
                                                   __half* __restrict__ oth,
                                                   __half* __restrict__ otl)
{
    __shared__ float t[32][33];
    const int bk = blockIdx.z;
    const int b = bk >> 3, hk = bk & 7;
    const int l0 = blockIdx.x * 32, d0 = blockIdx.y * 32;
    const int x = threadIdx.x & 31, y = threadIdx.x >> 5;
#pragma unroll
    for (int j = 0; j < 4; j++)
        t[y + 8 * j][x] = in[(size_t)(b * Ls + l0 + y + 8 * j) * instride + colbase + hk * Dd + d0 + x];
    __syncthreads();
    const int x2 = threadIdx.x & 15, yy = threadIdx.x >> 4;
#pragma unroll
    for (int j = 0; j < 2; j++) {
        int d = d0 + yy + 16 * j;
        uint32_t h, l;
        split2h(t[x2 * 2][yy + 16 * j], t[x2 * 2 + 1][yy + 16 * j], h, l);
        size_t off = (((size_t)bk * Dd + d) * Ls + l0 + x2 * 2) >> 1;
        ((uint32_t*)oth)[off] = h;
        ((uint32_t*)otl)[off] = l;
    }
}

__global__ __launch_bounds__(256) void conv_silu_split(const float* __restrict__ in,
                                                       int instride,
                                                       const float* __restrict__ w,
                                                       const float* __restrict__ bias,
                                                       __half* __restrict__ oh,
                                                       __half* __restrict__ ol,
                                                       float* __restrict__ of32,
                                                       int C, int npairs)
{
    int p = blockIdx.x * 256 + threadIdx.x;
    if (p >= npairs) return;
    const int Ch = C >> 1;
    int row = p / Ch;
    int c = (p - row * Ch) * 2;
    int l = row & (Ls - 1);
    const float* ip = in + (size_t)row * instride + c;
    float a0 = bias[c], a1 = bias[c + 1];
#pragma unroll
    for (int t = 0; t < 4; t++) {
        int ls = l + t - 3;
        if (ls >= 0) {
            a0 += w[c * 4 + t]       * ip[(ptrdiff_t)(t - 3) * instride];
            a1 += w[(c + 1) * 4 + t] * ip[(ptrdiff_t)(t - 3) * instride + 1];
        }
    }
    a0 = a0 / (1.f + expf(-a0));
    a1 = a1 / (1.f + expf(-a1));
    size_t oidx = (size_t)row * C + c;
    if (of32) { of32[oidx] = a0; of32[oidx + 1] = a1; }
    uint32_t h, lo;
    split2h(a0, a1, h, lo);
    ((uint32_t*)oh)[oidx >> 1] = h;
    if (ol) ((uint32_t*)ol)[oidx >> 1] = lo;
}

// =======================================================================
// attention MMA kernels (occupancy 2)
// =======================================================================
__global__ __launch_bounds__(256, 2) void kvloc_mma(const float* __restrict__ slope)
{
    extern __shared__ char sm[];
    const uint32_t sbase = smem_u32(sm);
    const int tid = threadIdx.x, wid = tid >> 5, lane = tid & 31;
    const int z = blockIdx.z;
    const int b = z / (Hh * NB), h = (z / NB) % Hh, c = z % NB, hk = h >> 1;
    const float s = slope[h];
    const int m0 = blockIdx.y * 128, n0 = blockIdx.x * 128;
    const int wm = (wid & 1) * 64, wn = (wid >> 1) * 32;
    const int t4 = lane & 3, tq = lane >> 2;
    const int fr = tid >> 3, fc = tid & 7;

    const __half* Avh = g_vTh + ((size_t)(b * 8 + hk) * Dd + m0) * Ls + c * BLK;
    const __half* Avl = g_vTl + ((size_t)(b * 8 + hk) * Dd + m0) * Ls + c * BLK;
    const float* BkT = g_kT + ((size_t)(b * 8 + hk) * Dd + n0) * Ls + c * BLK;
    const float ek = expf(s);

    float acc[4][4][4] = {};

#define FILLKV(st, buf) do {                                                              \
    const uint32_t sb = sbase + (buf) * STAGE_B;                                          \
    char* smb = sm + (buf) * STAGE_B;                                                     \
    const int k0 = (st) * 64;                                                             \
    fill_pair(sb + SA_H, sb + SA_L, Avh + k0, Avl + k0, Ls, fr, fc);                      \
    float kd0 = expf(-s * (float)(255 - (k0 + fc * 8)));                                  \
    fill_f32_decay(smb + SB_H, BkT + k0, Ls, fr, fc, kd0, ek);                            \
} while (0)

    FILLKV(0, 0); CPCOMMIT();
    FILLKV(1, 1); CPCOMMIT();
    for (int st = 0; st < 4; st++) {
        CPWAIT1();
        __syncthreads();
        stage_mma(sbase + (st & 1) * STAGE_B, acc, wm, wn, lane);
        __syncthreads();
        if (st + 2 < 4) FILLKV(st + 2, st & 1);
        CPCOMMIT();
    }
#undef FILLKV

    float* op = g_kv + (size_t)z * 65536;
#pragma unroll
    for (int mi = 0; mi < 4; mi++) {
        const int mA = m0 + wm + mi * 16 + tq, mB = mA + 8;
#pragma unroll
        for (int ni = 0; ni < 4; ni++) {
            const int cn = n0 + wn + ni * 8 + t4 * 2;
            *(float2*)(op + (size_t)mA * 256 + cn) = make_float2(acc[mi][ni][0], acc[mi][ni][1]);
            *(float2*)(op + (size_t)mB * 256 + cn) = make_float2(acc[mi][ni][2], acc[mi][ni][3]);
        }
    }
}

__global__ __launch_bounds__(256) void kvprefix_split(const float* __restrict__ slope)
{
    const int pidx = blockIdx.x * 256 + threadIdx.x;
    const int bh = pidx >> 15;
    const int off = (pidx & 32767) * 2;
    const int h = bh % Hh;
    const float bdec = expf(-slope[h] * (float)BLK);
    const float* p = g_kv + (size_t)bh * NB * 65536 + off;
    __half* oh = g_kvTh + (size_t)bh * NB * 65536 + off;
    float a0 = 0.f, a1 = 0.f;
#pragma unroll
    for (int c = 0; c < NB; c++) {
        float2 loc = *(const float2*)(p + (size_t)c * 65536);
        *(uint32_t*)(oh + (size_t)c * 65536) = round2h(a0, a1);
        a0 = a0 * bdec + loc.x;
        a1 = a1 * bdec + loc.y;
    }
}

__global__ __launch_bounds__(256, 2) void sc_mma(const float* __restrict__ slope)
{
    extern __shared__ char sm[];
    const uint32_t sbase = smem_u32(sm);
    const int tid = threadIdx.x, wid = tid >> 5, lane = tid & 31;
    const int z = blockIdx.z;
    const int b = z / (Hh * NB), h = (z / NB) % Hh, c = z % NB, hk = h >> 1;
    const float s = slope[h];
    const int m0 = blockIdx.y * 128, n0 = blockIdx.x * 128;

    __half* sh = g_sch + (size_t)z * 65536;
    __half* sl = g_scl + (size_t)z * 65536;

    // fully-masked tile (m < n everywhere): store zeros and exit
    if (m0 == 0 && n0 == 128) {
        uint32_t* sh32 = (uint32_t*)(sh + (size_t)m0 * 256 + n0);
        uint32_t* sl32 = (uint32_t*)(sl + (size_t)m0 * 256 + n0);
        for (int i = tid; i < 128 * 64; i += 256) {
            int row = i >> 6, col = i & 63;
            sh32[row * 128 + col] = 0u;
            sl32[row * 128 + col] = 0u;
        }
        return;
    }

    const int wm = (wid & 1) * 64, wn = (wid >> 1) * 32;
    const int t4 = lane & 3, tq = lane >> 2;
    const int fr = tid >> 3, fc = tid & 7;

    const __half* Ah = g_qh + (size_t)(b * Ls + c * BLK + m0) * HD + h * Dd;
    const __half* Al = g_ql + (size_t)(b * Ls + c * BLK + m0) * HD + h * Dd;
    const __half* Bh = g_kh + (size_t)(b * Ls + c * BLK + n0) * KD + hk * Dd;

    float acc[4][4][4] = {};

#define FILLSC(st, buf) do {                                                              \
    const uint32_t sb = sbase + (buf) * STAGE_B;                                          \
    const int k0 = (st) * 64;                                                             \
    fill_pair(sb + SA_H, sb + SA_L, Ah + k0, Al + k0, HD, fr, fc);                        \
    fill_one(sb + SB_H, Bh + k0, KD, fr, fc);                                             \
} while (0)

    FILLSC(0, 0); CPCOMMIT();
    FILLSC(1, 1); CPCOMMIT();
    for (int st = 0; st < 4; st++) {
        CPWAIT1();
        __syncthreads();
        stage_mma(sbase + (st & 1) * STAGE_B, acc, wm, wn, lane);
        __syncthreads();
        if (st + 2 < 4) FILLSC(st + 2, st & 1);
        CPCOMMIT();
    }
#undef FILLSC

#pragma unroll
    for (int mi = 0; mi < 4; mi++) {
        const int mA = m0 + wm + mi * 16 + tq, mB = mA + 8;
#pragma unroll
        for (int ni = 0; ni < 4; ni++) {
            const int cn = n0 + wn + ni * 8 + t4 * 2;
            float v0 = (mA >= cn)     ? acc[mi][ni][0] * expf(-s * (float)(mA - cn))     : 0.f;
            float v1 = (mA >= cn + 1) ? acc[mi][ni][1] * expf(-s * (float)(mA - cn - 1)) : 0.f;
            float v2 = (mB >= cn)     ? acc[mi][ni][2] * expf(-s * (float)(mB - cn))     : 0.f;
            float v3 = (mB >= cn + 1) ? acc[mi][ni][3] * expf(-s * (float)(mB - cn - 1)) : 0.f;
            uint32_t hh, ll;
            split2h(v0, v1, hh, ll);
            *(uint32_t*)(sh + (size_t)mA * 256 + cn) = hh;
            *(uint32_t*)(sl + (size_t)mA * 256 + cn) = ll;
            split2h(v2, v3, hh, ll);
            *(uint32_t*)(sh + (size_t)mB * 256 + cn) = hh;
            *(uint32_t*)(sl + (size_t)mB * 256 + cn) = ll;
        }
    }
}

// out: single 8-stage pipeline; qdec folded into staged A for stages 0-3
__global__ __launch_bounds__(256, 2) void out_mma(const float* __restrict__ slope)
{
    extern __shared__ char sm[];
    const uint32_t sbase = smem_u32(sm);
    const int tid = threadIdx.x, wid = tid >> 5, lane = tid & 31;
    const int z = blockIdx.z;
    const int b = z / (Hh * NB), h = (z / NB) % Hh, c = z % NB, hk = h >> 1;
    const float s = slope[h];
    const int m0 = blockIdx.y * 128, n0 = blockIdx.x * 128;
    const int wm = (wid & 1) * 64, wn = (wid >> 1) * 32;
    const int t4 = lane & 3, tq = lane >> 2;
    const int fr = tid >> 3, fc = tid & 7;

    const __half* Aqh = g_qh + (size_t)(b * Ls + c * BLK + m0) * HD + h * Dd;
    const __half* Aql = g_ql + (size_t)(b * Ls + c * BLK + m0) * HD + h * Dd;
    const __half* Bkv = g_kvTh + (size_t)z * 65536 + (size_t)n0 * 256;
    const __half* Ash = g_sch + (size_t)z * 65536 + (size_t)m0 * 256;
    const __half* Asl = g_scl + (size_t)z * 65536 + (size_t)m0 * 256;
    const __half* Bv  = g_vTh + ((size_t)(b * 8 + hk) * Dd + n0) * Ls + c * BLK;

    float acc[4][4][4] = {};

    // causal: for first m-tile, sc cols >= 128 are zero -> phase2 only stages 0-1
    const int NST = (m0 == 0) ? 6 : 8;

#define FILLOU(st, buf) do {                                                              \
    const uint32_t sb = sbase + (buf) * STAGE_B;                                          \
    char* smb = sm + (buf) * STAGE_B;                                                     \
    if ((st) < 4) {                                                                       \
        const int k0 = (st) * 64;                                                         \
        fill_q_qdec(smb + SA_H, smb + SA_L, Aqh + k0, Aql + k0, HD, fr, fc, s, m0);       \
        fill_one(sb + SB_H, Bkv + k0, 256, fr, fc);                                       \
    } else {                                                                              \
        const int k0 = ((st) - 4) * 64;                                                   \
        fill_pair(sb + SA_H, sb + SA_L, Ash + k0, Asl + k0, 256, fr, fc);                 \
        fill_one(sb + SB_H, Bv + k0, Ls, fr, fc);                                         \
    }                                                                                     \
} while (0)

    FILLOU(0, 0); CPCOMMIT();
    FILLOU(1, 1); CPCOMMIT();
    for (int st = 0; st < NST; st++) {
        CPWAIT1();
        __syncthreads();
        stage_mma(sbase + (st & 1) * STAGE_B, acc, wm, wn, lane);
        __syncthreads();
        if (st + 2 < NST) FILLOU(st + 2, st & 1);
        CPCOMMIT();
    }
#undef FILLOU

    float* op = g_o + (size_t)(b * Ls + c * BLK) * HD + h * Dd;
#pragma unroll
    for (int mi = 0; mi < 4; mi++) {
        const int mA = m0 + wm + mi * 16 + tq, mB = mA + 8;
#pragma unroll
        for (int ni = 0; ni < 4; ni++) {
            const int cn = n0 + wn + ni * 8 + t4 * 2;
            *(float2*)(op + (size_t)mA * HD + cn) = make_float2(acc[mi][ni][0], acc[mi][ni][1]);
            *(float2*)(op + (size_t)mB * HD + cn) = make_float2(acc[mi][ni][2], acc[mi][ni][3]);
        }
    }
}

// ---------------- SimpleRMSNorm + fp16 hi/lo split output ----------------
__global__ __launch_bounds__(256) void rmsnorm_split_kernel()
{
    const int row = blockIdx.x;
    const float* p = g_o + (size_t)row * HD;
    __half* oh = g_oh + (size_t)row * HD;
    __half* ol = g_ol + (size_t)row * HD;
    const int tid = threadIdx.x;
    float ss = 0.f;
    for (int i = tid; i < HD; i += 256) {
        float v = p[i];
        ss += v * v;
    }
#pragma unroll
    for (int off = 16; off > 0; off >>= 1) ss += __shfl_xor_sync(0xffffffffu, ss, off);
    __shared__ float red[8];
    __shared__ float scale_s;
    if ((tid & 31) == 0) red[tid >> 5] = ss;
    __syncthreads();
    if (tid == 0) {
        float tot = 0.f;
#pragma unroll
        for (int w = 0; w < 8; w++) tot += red[w];
        scale_s = rsqrtf(tot / (float)HD + 1e-6f);
    }
    __syncthreads();
    const float sc = scale_s;
    for (int i = tid * 2; i < HD; i += 512) {
        uint32_t h, l;
        split2h(p[i] * sc, p[i + 1] * sc, h, l);
        *(uint32_t*)(oh + i) = h;
        *(uint32_t*)(ol + i) = l;
    }
}

// ---------------- launcher ----------------
extern "C" void kernel_launch(void* const* d_in, const int* in_sizes, int n_in,
                              void* d_out, int out_size)
{
    const float* x     = (const float*)d_in[0];
    const float* Wq    = (const float*)d_in[1];
    const float* Wk    = (const float*)d_in[2];
    const float* Wv    = (const float*)d_in[3];
    const float* Wo    = (const float*)d_in[4];
    const float* cqw   = (const float*)d_in[5];
    const float* cqb   = (const float*)d_in[6];
    const float* ckw   = (const float*)d_in[7];
    const float* ckb   = (const float*)d_in[8];
    const float* slope = (const float*)d_in[9];
    float* out = (float*)d_out;

    static cudaStream_t s2 = nullptr;
    static cudaEvent_t evF, evWkv, evWq, evWo, evKV, evK, evP;
    if (!s2) {
        cudaStreamCreateWithFlags(&s2, cudaStreamNonBlocking);
        cudaEventCreateWithFlags(&evF,   cudaEventDisableTiming);
        cudaEventCreateWithFlags(&evWkv, cudaEventDisableTiming);
        cudaEventCreateWithFlags(&evWq,  cudaEventDisableTiming);
        cudaEventCreateWithFlags(&evWo,  cudaEventDisableTiming);
        cudaEventCreateWithFlags(&evKV,  cudaEventDisableTiming);
        cudaEventCreateWithFlags(&evK,   cudaEventDisableTiming);
        cudaEventCreateWithFlags(&evP,   cudaEventDisableTiming);
    }

    float *qkvpre, *kf, *kT;
    __half *xh, *xl, *wqkvh, *woh, *oh, *ol, *qh, *ql, *kh, *vth, *vtl;
    cudaGetSymbolAddress((void**)&qkvpre, g_qkvpre);
    cudaGetSymbolAddress((void**)&kf,     g_kf);
    cudaGetSymbolAddress((void**)&kT,     g_kT);
    cudaGetSymbolAddress((void**)&xh,     g_xh);
    cudaGetSymbolAddress((void**)&xl,     g_xl);
    cudaGetSymbolAddress((void**)&wqkvh,  g_wqkvh);
    cudaGetSymbolAddress((void**)&woh,    g_woh);
    cudaGetSymbolAddress((void**)&oh,     g_oh);
    cudaGetSymbolAddress((void**)&ol,     g_ol);
    cudaGetSymbolAddress((void**)&qh,     g_qh);
    cudaGetSymbolAddress((void**)&ql,     g_ql);
    cudaGetSymbolAddress((void**)&kh,     g_kh);
    cudaGetSymbolAddress((void**)&vth,    g_vTh);
    cudaGetSymbolAddress((void**)&vtl,    g_vTl);

    cudaFuncSetAttribute(hgemm2,    cudaFuncAttributeMaxDynamicSharedMemorySize, G2_SMEM);
    cudaFuncSetAttribute(kvloc_mma, cudaFuncAttributeMaxDynamicSharedMemorySize, HG_SMEM);
    cudaFuncSetAttribute(sc_mma,    cudaFuncAttributeMaxDynamicSharedMemorySize, HG_SMEM);
    cudaFuncSetAttribute(out_mma,   cudaFuncAttributeMaxDynamicSharedMemorySize, HG_SMEM);

    const int M = Bb * Ls;   // 4096

    // ---- fork: weight preparation on side stream (KV weights first) ----
    cudaEventRecord(evF, 0);
    cudaStreamWaitEvent(s2, evF, 0);
    tsplit<<<dim3(KD / 32, HIDd / 32), 256, 0, s2>>>(Wk, wqkvh + (size_t)HD * HIDd, HIDd, KD);
    tsplit<<<dim3(KD / 32, HIDd / 32), 256, 0, s2>>>(Wv, wqkvh + (size_t)(HD + KD) * HIDd, HIDd, KD);
    cudaEventRecord(evWkv, s2);
    tsplit<<<dim3(HD / 32, HIDd / 32), 256, 0, s2>>>(Wq, wqkvh, HIDd, HD);
    cudaEventRecord(evWq, s2);
    tsplit<<<dim3(HIDd / 32, HD / 32), 256, 0, s2>>>(Wo, woh, HD, HIDd);
    cudaEventRecord(evWo, s2);

    // ---- main: x split, then KV projection FIRST ----
    convsplit<<<(M * HIDd / 4 + 255) / 256, 256>>>(x, xh, xl, M * HIDd / 4);
    cudaStreamWaitEvent(0, evWkv, 0);
    hgemm2<<<dim3((KD + KD) / 256, M / 128), 256, G2_SMEM>>>(
        xh, xl, wqkvh + (size_t)HD * HIDd, qkvpre + HD, M, HIDd, NQKV);
    cudaEventRecord(evKV, 0);

    // ---- main: Q projection (overlaps side-stream kv chain) ----
    cudaStreamWaitEvent(0, evWq, 0);
    hgemm2<<<dim3(HD / 256, M / 128), 256, G2_SMEM>>>(
        xh, xl, wqkvh, qkvpre, M, HIDd, NQKV);

    // ---- side stream: full kv chain, starts as soon as KV cols exist ----
    cudaStreamWaitEvent(s2, evKV, 0);
    conv_silu_split<<<(M * KD / 2 + 255) / 256, 256, 0, s2>>>(qkvpre + HD, NQKV, ckw, ckb, kh, nullptr, kf, KD, M * KD / 2);
    cudaEventRecord(evK, s2);
    trans_split<<<dim3(Ls / 32, Dd / 32, 16), 256, 0, s2>>>(qkvpre, NQKV, HD + KD, vth, vtl);
    trans_f32<<<dim3(Ls / 32, Dd / 32, 16), 256, 0, s2>>>(kf, kT);
    kvloc_mma<<<dim3(2, 2, Bb * Hh * NB), 256, HG_SMEM, s2>>>(slope);
    kvprefix_split<<<(Bb * Hh * 32768) / 256, 256, 0, s2>>>(slope);
    cudaEventRecord(evP, s2);

    // ---- main: conv_q -> sc -> out ----
    conv_silu_split<<<(M * HD / 2 + 255) / 256, 256>>>(qkvpre, NQKV, cqw, cqb, qh, ql, nullptr, HD, M * HD / 2);
    cudaStreamWaitEvent(0, evK, 0);
    sc_mma<<<dim3(2, 2, Bb * Hh * NB), 256, HG_SMEM>>>(slope);
    cudaStreamWaitEvent(0, evP, 0);
    out_mma<<<dim3(2, 2, Bb * Hh * NB), 256, HG_SMEM>>>(slope);

    // norm + split + output projection
    rmsnorm_split_kernel<<<M, 256>>>();
    cudaStreamWaitEvent(0, evWo, 0);
    hgemm2<<<dim3(HIDd / 256, M / 128), 256, G2_SMEM>>>(oh, ol, woh, out, M, HD, HIDd);
}

// round 17
// speedup vs baseline: 1.0176x; 1.0176x over previous
#include <cuda_runtime.h>
#include <cuda_fp16.h>
#include <cstdint>

#define Bb   2
#define Ls   2048
#define Hh   16
#define Dd   256
#define HD   4096   // H*D
#define KD   2048   // HKV*D
#define HIDd 2048
#define NB   8
#define BLK  256
#define NQKV 8192   // HD + KD + KD

// ---------------- scratch (static device memory; no allocs) ----------------
static __device__ __align__(128) float g_qkvpre[Bb * Ls * NQKV];
static __device__ __align__(128) float g_kf  [Bb * Ls * KD];
static __device__ __align__(128) float g_kv  [Bb * Hh * NB * Dd * Dd];
static __device__ __align__(128) float g_o   [Bb * Ls * HD];
static __device__ __align__(128) float g_kT  [16 * Dd * Ls];

static __device__ __align__(128) __half g_xh   [Bb * Ls * HIDd];
static __device__ __align__(128) __half g_xl   [Bb * Ls * HIDd];
static __device__ __align__(128) __half g_wqkvh[NQKV * HIDd];
static __device__ __align__(128) __half g_woh  [HIDd * HD];
static __device__ __align__(128) __half g_oh   [Bb * Ls * HD];
static __device__ __align__(128) __half g_ol   [Bb * Ls * HD];
static __device__ __align__(128) __half g_qh   [Bb * Ls * HD];
static __device__ __align__(128) __half g_ql   [Bb * Ls * HD];
static __device__ __align__(128) __half g_kh   [Bb * Ls * KD];
static __device__ __align__(128) __half g_vTh  [16 * Dd * Ls];
static __device__ __align__(128) __half g_vTl  [16 * Dd * Ls];
static __device__ __align__(128) __half g_kvTh [Bb * Hh * NB * Dd * Dd];
static __device__ __align__(128) __half g_sch  [Bb * Hh * NB * BLK * BLK];
static __device__ __align__(128) __half g_scl  [Bb * Hh * NB * BLK * BLK];

// =======================================================================
// helpers
// =======================================================================
__device__ __forceinline__ uint32_t smem_u32(const void* p) {
    uint32_t a;
    asm("{ .reg .u64 t; cvta.to.shared.u64 t, %1; cvt.u32.u64 %0, t; }" : "=r"(a) : "l"(p));
    return a;
}
__device__ __forceinline__ void split2h(float x0, float x1, uint32_t& hi, uint32_t& lo) {
    __half2 h = __floats2half2_rn(x0, x1);
    float r0 = x0 - __half2float(__low2half(h));
    float r1 = x1 - __half2float(__high2half(h));
    __half2 l = __floats2half2_rn(r0, r1);
    hi = *reinterpret_cast<uint32_t*>(&h);
    lo = *reinterpret_cast<uint32_t*>(&l);
}
__device__ __forceinline__ uint32_t round2h(float x0, float x1) {
    __half2 h = __floats2half2_rn(x0, x1);
    return *reinterpret_cast<uint32_t*>(&h);
}
#define CPA16(dst, src) asm volatile("cp.async.cg.shared.global [%0], [%1], 16;" :: "r"(dst), "l"(src))
#define CPCOMMIT()      asm volatile("cp.async.commit_group;" ::: "memory")
#define CPWAIT1()       asm volatile("cp.async.wait_group 1;" ::: "memory")
__device__ __forceinline__ void ldsm4(uint32_t a, uint32_t* r) {
    asm volatile("ldmatrix.sync.aligned.m8n8.x4.shared.b16 {%0,%1,%2,%3}, [%4];"
                 : "=r"(r[0]), "=r"(r[1]), "=r"(r[2]), "=r"(r[3]) : "r"(a));
}
__device__ __forceinline__ void mma16816(float* d, const uint32_t* a, const uint32_t* b) {
    asm volatile("mma.sync.aligned.m16n8k16.row.col.f32.f16.f16.f32 "
                 "{%0,%1,%2,%3}, {%4,%5,%6,%7}, {%8,%9}, {%0,%1,%2,%3};"
                 : "+f"(d[0]), "+f"(d[1]), "+f"(d[2]), "+f"(d[3])
                 : "r"(a[0]), "r"(a[1]), "r"(a[2]), "r"(a[3]), "r"(b[0]), "r"(b[1]));
}

// ---------- 128x128-tile layout (attention kernels): A hi/lo + B hi ----------
#define SA_H 0
#define SA_L 16384
#define SB_H 32768
#define STAGE_B 49152
#define HG_SMEM (2 * STAGE_B)

__device__ __forceinline__ void stage_mma(uint32_t sb, float acc[4][4][4],
                                          int wm, int wn, int lane)
{
    const int rA = lane & 15, kA = lane >> 4;
    const int rB = (lane & 7) | ((lane & 16) >> 1), kB = (lane >> 3) & 1;
    const int e = lane & 7;
    const uint32_t baseA = sb + (uint32_t)((wm + rA) * 128);
    const uint32_t baseB = sb + (uint32_t)((wn + rB) * 128);
#pragma unroll
    for (int kk = 0; kk < 4; kk++) {
        const uint32_t cA = (uint32_t)(((2 * kk + kA) ^ e) << 4);
        const uint32_t cB = (uint32_t)(((2 * kk + kB) ^ e) << 4);
        uint32_t ah[4][4], al[4][4], bh[2][4];
#pragma unroll
        for (int mi = 0; mi < 4; mi++) {
            ldsm4(baseA + SA_H + mi * 2048 + cA, ah[mi]);
            ldsm4(baseA + SA_L + mi * 2048 + cA, al[mi]);
        }
#pragma unroll
        for (int nj = 0; nj < 2; nj++)
            ldsm4(baseB + SB_H + nj * 2048 + cB, bh[nj]);
#pragma unroll
        for (int mi = 0; mi < 4; mi++)
#pragma unroll
            for (int ni = 0; ni < 4; ni++) {
                const uint32_t* bph = &bh[ni >> 1][(ni & 1) * 2];
                mma16816(acc[mi][ni], ah[mi], bph);
                mma16816(acc[mi][ni], al[mi], bph);
            }
    }
}

__device__ __forceinline__ void fill_pair(uint32_t sb_h, uint32_t sb_l,
                                          const __half* gh, const __half* gl,
                                          size_t stride, int fr, int fc)
{
#pragma unroll
    for (int i = 0; i < 4; i++) {
        int r = fr + 32 * i;
        uint32_t doff = (uint32_t)(r * 128 + ((fc ^ (r & 7)) << 4));
        size_t so = (size_t)r * stride + fc * 8;
        CPA16(sb_h + doff, gh + so);
        CPA16(sb_l + doff, gl + so);
    }
}

__device__ __forceinline__ void fill_one(uint32_t sb_h, const __half* gh,
                                         size_t stride, int fr, int fc)
{
#pragma unroll
    for (int i = 0; i < 4; i++) {
        int r = fr + 32 * i;
        uint32_t doff = (uint32_t)(r * 128 + ((fc ^ (r & 7)) << 4));
        CPA16(sb_h + doff, gh + (size_t)r * stride + fc * 8);
    }
}

__device__ __forceinline__ void fill_f32_decay(char* smh, const float* g, size_t stride,
                                               int fr, int fc, float kd0, float ek)
{
    float kd[8];
    kd[0] = kd0;
#pragma unroll
    for (int j = 1; j < 8; j++) kd[j] = kd[j - 1] * ek;
#pragma unroll
    for (int i = 0; i < 4; i++) {
        int r = fr + 32 * i;
        uint32_t doff = (uint32_t)(r * 128 + ((fc ^ (r & 7)) << 4));
        const float* sp = g + (size_t)r * stride + fc * 8;
        float4 u = *(const float4*)sp;
        float4 w = *(const float4*)(sp + 4);
        uint4 hi;
        hi.x = round2h(u.x * kd[0], u.y * kd[1]);
        hi.y = round2h(u.z * kd[2], u.w * kd[3]);
        hi.z = round2h(w.x * kd[4], w.y * kd[5]);
        hi.w = round2h(w.z * kd[6], w.w * kd[7]);
        *(uint4*)(smh + doff) = hi;
    }
}

// manual A staging: reconstruct q from hi/lo, scale by qdec(row), re-split
__device__ __forceinline__ void fill_q_qdec(char* smh, char* sml,
                                            const __half* gh, const __half* gl,
                                            size_t stride, int fr, int fc,
                                            float s, int mbase)
{
#pragma unroll
    for (int i = 0; i < 4; i++) {
        int r = fr + 32 * i;
        uint32_t doff = (uint32_t)(r * 128 + ((fc ^ (r & 7)) << 4));
        const float qd = expf(-s * (float)(mbase + r + 1));
        uint4 hv = *(const uint4*)(gh + (size_t)r * stride + fc * 8);
        uint4 lv = *(const uint4*)(gl + (size_t)r * stride + fc * 8);
        uint4 oh, ol;
        const uint32_t* hp = &hv.x;
        const uint32_t* lp = &lv.x;
        uint32_t* op = &oh.x;
        uint32_t* op2 = &ol.x;
#pragma unroll
        for (int j = 0; j < 4; j++) {
            __half2 h2 = *reinterpret_cast<const __half2*>(&hp[j]);
            __half2 l2 = *reinterpret_cast<const __half2*>(&lp[j]);
            float v0 = (__half2float(__low2half(h2)) + __half2float(__low2half(l2))) * qd;
            float v1 = (__half2float(__high2half(h2)) + __half2float(__high2half(l2))) * qd;
            split2h(v0, v1, op[j], op2[j]);
        }
        *(uint4*)(smh + doff) = oh;
        *(uint4*)(sml + doff) = ol;
    }
}

// =======================================================================
// hgemm2: 128(M) x 256(N), BK=64, 2-stage; C row stride = ldc
// =======================================================================
#define G2_SA_H 0
#define G2_SA_L 16384
#define G2_SB_H 32768
#define G2_STAGE 65536
#define G2_SMEM (2 * G2_STAGE)

__global__ __launch_bounds__(256, 1) void hgemm2(const __half* __restrict__ Ah,
                                                 const __half* __restrict__ Al,
                                                 const __half* __restrict__ Bh,
                                                 float* __restrict__ C,
                                                 int M, int K, int ldc)
{
    extern __shared__ char sm[];
    const uint32_t sbase = smem_u32(sm);
    const int tid = threadIdx.x, wid = tid >> 5, lane = tid & 31;
    const int m0 = blockIdx.y * 128, n0 = blockIdx.x * 256;
    const int wm = (wid & 1) * 64, wn = (wid >> 1) * 64;
    const int t4 = lane & 3, tq = lane >> 2;
    const int fr = tid >> 3, fc = tid & 7;

    const int rA = lane & 15, kA = lane >> 4;
    const int rB = (lane & 7) | ((lane & 16) >> 1), kB = (lane >> 3) & 1;
    const int e = lane & 7;

    float acc[4][8][4];
#pragma unroll
    for (int a = 0; a < 4; a++)
#pragma unroll
        for (int b = 0; b < 8; b++)
#pragma unroll
            for (int c = 0; c < 4; c++) acc[a][b][c] = 0.f;

#define FILL2(s, buf) do {                                                                \
    const uint32_t sb = sbase + (buf) * G2_STAGE;                                         \
    const int k0 = (s) * 64;                                                              \
    _Pragma("unroll")                                                                     \
    for (int i = 0; i < 4; i++) {                                                         \
        int r = fr + 32 * i;                                                              \
        uint32_t doff = (uint32_t)(r * 128 + ((fc ^ (r & 7)) << 4));                      \
        size_t so = (size_t)(m0 + r) * K + k0 + fc * 8;                                   \
        CPA16(sb + G2_SA_H + doff, Ah + so);                                              \
        CPA16(sb + G2_SA_L + doff, Al + so);                                              \
    }                                                                                     \
    _Pragma("unroll")                                                                     \
    for (int i = 0; i < 8; i++) {                                                         \
        int r = fr + 32 * i;                                                              \
        uint32_t doff = (uint32_t)(r * 128 + ((fc ^ (r & 7)) << 4));                      \
        CPA16(sb + G2_SB_H + doff, Bh + (size_t)(n0 + r) * K + k0 + fc * 8);              \
    }                                                                                     \
} while (0)

    const int S = K / 64;
    FILL2(0, 0); CPCOMMIT();
    FILL2(1, 1); CPCOMMIT();

    for (int s = 0; s < S; s++) {
        CPWAIT1();
        __syncthreads();
        const uint32_t sb = sbase + (s & 1) * G2_STAGE;
        const uint32_t baseA = sb + (uint32_t)((wm + rA) * 128);
        const uint32_t baseB = sb + (uint32_t)((wn + rB) * 128);
#pragma unroll
        for (int kk = 0; kk < 4; kk++) {
            const uint32_t cA = (uint32_t)(((2 * kk + kA) ^ e) << 4);
            const uint32_t cB = (uint32_t)(((2 * kk + kB) ^ e) << 4);
            uint32_t ah[4][4], al[4][4], bh[4][4];
#pragma unroll
            for (int mi = 0; mi < 4; mi++) {
                ldsm4(baseA + G2_SA_H + mi * 2048 + cA, ah[mi]);
                ldsm4(baseA + G2_SA_L + mi * 2048 + cA, al[mi]);
            }
#pragma unroll
            for (int nj = 0; nj < 4; nj++)
                ldsm4(baseB + G2_SB_H + nj * 2048 + cB, bh[nj]);
#pragma unroll
            for (int mi = 0; mi < 4; mi++)
#pragma unroll
                for (int ni = 0; ni < 8; ni++) {
                    const uint32_t* bph = &bh[ni >> 1][(ni & 1) * 2];
                    mma16816(acc[mi][ni], ah[mi], bph);
                    mma16816(acc[mi][ni], al[mi], bph);
                }
        }
        __syncthreads();
        if (s + 2 < S) FILL2(s + 2, s & 1);
        CPCOMMIT();
    }
#undef FILL2

#pragma unroll
    for (int mi = 0; mi < 4; mi++) {
        const int m = m0 + wm + mi * 16 + tq;
#pragma unroll
        for (int ni = 0; ni < 8; ni++) {
            const int n = n0 + wn + ni * 8 + t4 * 2;
            *(float2*)(C + (size_t)m * ldc + n)       = make_float2(acc[mi][ni][0], acc[mi][ni][1]);
            *(float2*)(C + (size_t)(m + 8) * ldc + n) = make_float2(acc[mi][ni][2], acc[mi][ni][3]);
        }
    }
}

// =======================================================================
// convert kernels
// =======================================================================
__global__ __launch_bounds__(256) void convsplit(const float* __restrict__ in,
                                                 __half* __restrict__ hi,
                                                 __half* __restrict__ lo, int n4)
{
    int i = blockIdx.x * 256 + threadIdx.x;
    if (i >= n4) return;
    float4 v = ((const float4*)in)[i];
    uint2 h, l;
    split2h(v.x, v.y, h.x, l.x);
    split2h(v.z, v.w, h.y, l.y);
    ((uint2*)hi)[i] = h;
    ((uint2*)lo)[i] = l;
}

__global__ __launch_bounds__(256) void tsplit(const float* __restrict__ W,
                                              __half* __restrict__ th,
                                              int Kd, int Nd)
{
    __shared__ float t[32][33];
    const int bxn = blockIdx.x * 32;
    const int byk = blockIdx.y * 32;
    const int x = threadIdx.x & 31, y = threadIdx.x >> 5;
#pragma unroll
    for (int j = 0; j < 4; j++)
        t[y + 8 * j][x] = W[(size_t)(byk + y + 8 * j) * Nd + bxn + x];
    __syncthreads();
    const int n = bxn + x;
    uint2 h;
    h.x = round2h(t[y * 4 + 0][x], t[y * 4 + 1][x]);
    h.y = round2h(t[y * 4 + 2][x], t[y * 4 + 3][x]);
    ((uint2*)th)[((size_t)n * Kd + byk + y * 4) >> 2] = h;
}

__global__ __launch_bounds__(256) void trans_f32(const float* __restrict__ in,
                                                 float* __restrict__ out)
{
    __shared__ float t[32][33];
    const int bk = blockIdx.z;
    const int b = bk >> 3, hk = bk & 7;
    const int l0 = blockIdx.x * 32, d0 = blockIdx.y * 32;
    const int x = threadIdx.x & 31, y = threadIdx.x >> 5;
#pragma unroll
    for (int j = 0; j < 4; j++)
        t[y + 8 * j][x] = in[(size_t)(b * Ls + l0 + y + 8 * j) * KD + hk * Dd + d0 + x];
    __syncthreads();
#pragma unroll
    for (int j = 0; j < 4; j++) {
        int d = d0 + y + 8 * j;
        out[((size_t)bk * Dd + d) * Ls + l0 + x] = t[x][y + 8 * j];
    }
}

__global__ __launch_bounds__(256) void trans_split(const float* __restrict__ in,
                                                   int instride, int colbase,
                                                   __half* __restrict__ oth,
                                                   __half* __restrict__ otl)
{
    __shared__ float t[32][33];
    const int bk = blockIdx.z;
    const int b = bk >> 3, hk = bk & 7;
    const int l0 = blockIdx.x * 32, d0 = blockIdx.y * 32;
    const int x = threadIdx.x & 31, y = threadIdx.x >> 5;
#pragma unroll
    for (int j = 0; j < 4; j++)
        t[y + 8 * j][x] = in[(size_t)(b * Ls + l0 + y + 8 * j) * instride + colbase + hk * Dd + d0 + x];
    __syncthreads();
    const int x2 = threadIdx.x & 15, yy = threadIdx.x >> 4;
#pragma unroll
    for (int j = 0; j < 2; j++) {
        int d = d0 + yy + 16 * j;
        uint32_t h, l;
        split2h(t[x2 * 2][yy + 16 * j], t[x2 * 2 + 1][yy + 16 * j], h, l);
        size_t off = (((size_t)bk * Dd + d) * Ls + l0 + x2 * 2) >> 1;
        ((uint32_t*)oth)[off] = h;
        ((uint32_t*)otl)[off] = l;
    }
}

__global__ __launch_bounds__(256) void conv_silu_split(const float* __restrict__ in,
                                                       int instride,
                                                       const float* __restrict__ w,
                                                       const float* __restrict__ bias,
                                                       __half* __restrict__ oh,
                                                       __half* __restrict__ ol,
                                                       float* __restrict__ of32,
                                                       int C, int npairs)
{
    int p = blockIdx.x * 256 + threadIdx.x;
    if (p >= npairs) return;
    const int Ch = C >> 1;
    int row = p / Ch;
    int c = (p - row * Ch) * 2;
    int l = row & (Ls - 1);
    const float* ip = in + (size_t)row * instride + c;
    float a0 = bias[c], a1 = bias[c + 1];
#pragma unroll
    for (int t = 0; t < 4; t++) {
        int ls = l + t - 3;
        if (ls >= 0) {
            a0 += w[c * 4 + t]       * ip[(ptrdiff_t)(t - 3) * instride];
            a1 += w[(c + 1) * 4 + t] * ip[(ptrdiff_t)(t - 3) * instride + 1];
        }
    }
    a0 = a0 / (1.f + expf(-a0));
    a1 = a1 / (1.f + expf(-a1));
    size_t oidx = (size_t)row * C + c;
    if (of32) { of32[oidx] = a0; of32[oidx + 1] = a1; }
    uint32_t h, lo;
    split2h(a0, a1, h, lo);
    ((uint32_t*)oh)[oidx >> 1] = h;
    if (ol) ((uint32_t*)ol)[oidx >> 1] = lo;
}

// =======================================================================
// attention MMA kernels (occupancy 2)
// =======================================================================
__global__ __launch_bounds__(256, 2) void kvloc_mma(const float* __restrict__ slope)
{
    extern __shared__ char sm[];
    const uint32_t sbase = smem_u32(sm);
    const int tid = threadIdx.x, wid = tid >> 5, lane = tid & 31;
    const int z = blockIdx.z;
    const int b = z / (Hh * NB), h = (z / NB) % Hh, c = z % NB, hk = h >> 1;
    const float s = slope[h];
    const int m0 = blockIdx.y * 128, n0 = blockIdx.x * 128;
    const int wm = (wid & 1) * 64, wn = (wid >> 1) * 32;
    const int t4 = lane & 3, tq = lane >> 2;
    const int fr = tid >> 3, fc = tid & 7;

    const __half* Avh = g_vTh + ((size_t)(b * 8 + hk) * Dd + m0) * Ls + c * BLK;
    const __half* Avl = g_vTl + ((size_t)(b * 8 + hk) * Dd + m0) * Ls + c * BLK;
    const float* BkT = g_kT + ((size_t)(b * 8 + hk) * Dd + n0) * Ls + c * BLK;
    const float ek = expf(s);

    float acc[4][4][4] = {};

#define FILLKV(st, buf) do {                                                              \
    const uint32_t sb = sbase + (buf) * STAGE_B;                                          \
    char* smb = sm + (buf) * STAGE_B;                                                     \
    const int k0 = (st) * 64;                                                             \
    fill_pair(sb + SA_H, sb + SA_L, Avh + k0, Avl + k0, Ls, fr, fc);                      \
    float kd0 = expf(-s * (float)(255 - (k0 + fc * 8)));                                  \
    fill_f32_decay(smb + SB_H, BkT + k0, Ls, fr, fc, kd0, ek);                            \
} while (0)

    FILLKV(0, 0); CPCOMMIT();
    FILLKV(1, 1); CPCOMMIT();
    for (int st = 0; st < 4; st++) {
        CPWAIT1();
        __syncthreads();
        stage_mma(sbase + (st & 1) * STAGE_B, acc, wm, wn, lane);
        __syncthreads();
        if (st + 2 < 4) FILLKV(st + 2, st & 1);
        CPCOMMIT();
    }
#undef FILLKV

    float* op = g_kv + (size_t)z * 65536;
#pragma unroll
    for (int mi = 0; mi < 4; mi++) {
        const int mA = m0 + wm + mi * 16 + tq, mB = mA + 8;
#pragma unroll
        for (int ni = 0; ni < 4; ni++) {
            const int cn = n0 + wn + ni * 8 + t4 * 2;
            *(float2*)(op + (size_t)mA * 256 + cn) = make_float2(acc[mi][ni][0], acc[mi][ni][1]);
            *(float2*)(op + (size_t)mB * 256 + cn) = make_float2(acc[mi][ni][2], acc[mi][ni][3]);
        }
    }
}

__global__ __launch_bounds__(256) void kvprefix_split(const float* __restrict__ slope)
{
    const int pidx = blockIdx.x * 256 + threadIdx.x;
    const int bh = pidx >> 15;
    const int off = (pidx & 32767) * 2;
    const int h = bh % Hh;
    const float bdec = expf(-slope[h] * (float)BLK);
    const float* p = g_kv + (size_t)bh * NB * 65536 + off;
    __half* oh = g_kvTh + (size_t)bh * NB * 65536 + off;
    float a0 = 0.f, a1 = 0.f;
#pragma unroll
    for (int c = 0; c < NB; c++) {
        float2 loc = *(const float2*)(p + (size_t)c * 65536);
        *(uint32_t*)(oh + (size_t)c * 65536) = round2h(a0, a1);
        a0 = a0 * bdec + loc.x;
        a1 = a1 * bdec + loc.y;
    }
}

__global__ __launch_bounds__(256, 2) void sc_mma(const float* __restrict__ slope)
{
    extern __shared__ char sm[];
    const uint32_t sbase = smem_u32(sm);
    const int tid = threadIdx.x, wid = tid >> 5, lane = tid & 31;
    const int z = blockIdx.z;
    const int b = z / (Hh * NB), h = (z / NB) % Hh, c = z % NB, hk = h >> 1;
    const float s = slope[h];
    const int m0 = blockIdx.y * 128, n0 = blockIdx.x * 128;

    // fully-masked tile: never read downstream (out m0==0 path reads only
    // sc cols 0..127) -> skip entirely
    if (m0 == 0 && n0 == 128) return;

    __half* sh = g_sch + (size_t)z * 65536;
    __half* sl = g_scl + (size_t)z * 65536;

    const int wm = (wid & 1) * 64, wn = (wid >> 1) * 32;
    const int t4 = lane & 3, tq = lane >> 2;
    const int fr = tid >> 3, fc = tid & 7;

    const __half* Ah = g_qh + (size_t)(b * Ls + c * BLK + m0) * HD + h * Dd;
    const __half* Al = g_ql + (size_t)(b * Ls + c * BLK + m0) * HD + h * Dd;
    const __half* Bh = g_kh + (size_t)(b * Ls + c * BLK + n0) * KD + hk * Dd;

    float acc[4][4][4] = {};

#define FILLSC(st, buf) do {                                                              \
    const uint32_t sb = sbase + (buf) * STAGE_B;                                          \
    const int k0 = (st) * 64;                                                             \
    fill_pair(sb + SA_H, sb + SA_L, Ah + k0, Al + k0, HD, fr, fc);                        \
    fill_one(sb + SB_H, Bh + k0, KD, fr, fc);                                             \
} while (0)

    FILLSC(0, 0); CPCOMMIT();
    FILLSC(1, 1); CPCOMMIT();
    for (int st = 0; st < 4; st++) {
        CPWAIT1();
        __syncthreads();
        stage_mma(sbase + (st & 1) * STAGE_B, acc, wm, wn, lane);
        __syncthreads();
        if (st + 2 < 4) FILLSC(st + 2, st & 1);
        CPCOMMIT();
    }
#undef FILLSC

#pragma unroll
    for (int mi = 0; mi < 4; mi++) {
        const int mA = m0 + wm + mi * 16 + tq, mB = mA + 8;
#pragma unroll
        for (int ni = 0; ni < 4; ni++) {
            const int cn = n0 + wn + ni * 8 + t4 * 2;
            float v0 = (mA >= cn)     ? acc[mi][ni][0] * expf(-s * (float)(mA - cn))     : 0.f;
            float v1 = (mA >= cn + 1) ? acc[mi][ni][1] * expf(-s * (float)(mA - cn - 1)) : 0.f;
            float v2 = (mB >= cn)     ? acc[mi][ni][2] * expf(-s * (float)(mB - cn))     : 0.f;
            float v3 = (mB >= cn + 1) ? acc[mi][ni][3] * expf(-s * (float)(mB - cn - 1)) : 0.f;
            uint32_t hh, ll;
            split2h(v0, v1, hh, ll);
            *(uint32_t*)(sh + (size_t)mA * 256 + cn) = hh;
            *(uint32_t*)(sl + (size_t)mA * 256 + cn) = ll;
            split2h(v2, v3, hh, ll);
            *(uint32_t*)(sh + (size_t)mB * 256 + cn) = hh;
            *(uint32_t*)(sl + (size_t)mB * 256 + cn) = ll;
        }
    }
}

// out: single 8-stage pipeline; qdec folded into staged A for stages 0-3
__global__ __launch_bounds__(256, 2) void out_mma(const float* __restrict__ slope, int zbase)
{
    extern __shared__ char sm[];
    const uint32_t sbase = smem_u32(sm);
    const int tid = threadIdx.x, wid = tid >> 5, lane = tid & 31;
    const int z = blockIdx.z + zbase;
    const int b = z / (Hh * NB), h = (z / NB) % Hh, c = z % NB, hk = h >> 1;
    const float s = slope[h];
    const int m0 = blockIdx.y * 128, n0 = blockIdx.x * 128;
    const int wm = (wid & 1) * 64, wn = (wid >> 1) * 32;
    const int t4 = lane & 3, tq = lane >> 2;
    const int fr = tid >> 3, fc = tid & 7;

    const __half* Aqh = g_qh + (size_t)(b * Ls + c * BLK + m0) * HD + h * Dd;
    const __half* Aql = g_ql + (size_t)(b * Ls + c * BLK + m0) * HD + h * Dd;
    const __half* Bkv = g_kvTh + (size_t)z * 65536 + (size_t)n0 * 256;
    const __half* Ash = g_sch + (size_t)z * 65536 + (size_t)m0 * 256;
    const __half* Asl = g_scl + (size_t)z * 65536 + (size_t)m0 * 256;
    const __half* Bv  = g_vTh + ((size_t)(b * 8 + hk) * Dd + n0) * Ls + c * BLK;

    float acc[4][4][4] = {};

    // causal: for first m-tile, sc cols >= 128 are zero -> phase2 only stages 0-1
    const int NST = (m0 == 0) ? 6 : 8;

#define FILLOU(st, buf) do {                                                              \
    const uint32_t sb = sbase + (buf) * STAGE_B;                                          \
    char* smb = sm + (buf) * STAGE_B;                                                     \
    if ((st) < 4) {                                                                       \
        const int k0 = (st) * 64;                                                         \
        fill_q_qdec(smb + SA_H, smb + SA_L, Aqh + k0, Aql + k0, HD, fr, fc, s, m0);       \
        fill_one(sb + SB_H, Bkv + k0, 256, fr, fc);                                       \
    } else {                                                                              \
        const int k0 = ((st) - 4) * 64;                                                   \
        fill_pair(sb + SA_H, sb + SA_L, Ash + k0, Asl + k0, 256, fr, fc);                 \
        fill_one(sb + SB_H, Bv + k0, Ls, fr, fc);                                         \
    }                                                                                     \
} while (0)

    FILLOU(0, 0); CPCOMMIT();
    FILLOU(1, 1); CPCOMMIT();
    for (int st = 0; st < NST; st++) {
        CPWAIT1();
        __syncthreads();
        stage_mma(sbase + (st & 1) * STAGE_B, acc, wm, wn, lane);
        __syncthreads();
        if (st + 2 < NST) FILLOU(st + 2, st & 1);
        CPCOMMIT();
    }
#undef FILLOU

    float* op = g_o + (size_t)(b * Ls + c * BLK) * HD + h * Dd;
#pragma unroll
    for (int mi = 0; mi < 4; mi++) {
        const int mA = m0 + wm + mi * 16 + tq, mB = mA + 8;
#pragma unroll
        for (int ni = 0; ni < 4; ni++) {
            const int cn = n0 + wn + ni * 8 + t4 * 2;
            *(float2*)(op + (size_t)mA * HD + cn) = make_float2(acc[mi][ni][0], acc[mi][ni][1]);
            *(float2*)(op + (size_t)mB * HD + cn) = make_float2(acc[mi][ni][2], acc[mi][ni][3]);
        }
    }
}

// ---------------- SimpleRMSNorm + fp16 hi/lo split output ----------------
__global__ __launch_bounds__(256) void rmsnorm_split_kernel(int rbase)
{
    const int row = blockIdx.x + rbase;
    const float* p = g_o + (size_t)row * HD;
    __half* oh = g_oh + (size_t)row * HD;
    __half* ol = g_ol + (size_t)row * HD;
    const int tid = threadIdx.x;
    float ss = 0.f;
    for (int i = tid; i < HD; i += 256) {
        float v = p[i];
        ss += v * v;
    }
#pragma unroll
    for (int off = 16; off > 0; off >>= 1) ss += __shfl_xor_sync(0xffffffffu, ss, off);
    __shared__ float red[8];
    __shared__ float scale_s;
    if ((tid & 31) == 0) red[tid >> 5] = ss;
    __syncthreads();
    if (tid == 0) {
        float tot = 0.f;
#pragma unroll
        for (int w = 0; w < 8; w++) tot += red[w];
        scale_s = rsqrtf(tot / (float)HD + 1e-6f);
    }
    __syncthreads();
    const float sc = scale_s;
    for (int i = tid * 2; i < HD; i += 512) {
        uint32_t h, l;
        split2h(p[i] * sc, p[i + 1] * sc, h, l);
        *(uint32_t*)(oh + i) = h;
        *(uint32_t*)(ol + i) = l;
    }
}

// ---------------- launcher ----------------
extern "C" void kernel_launch(void* const* d_in, const int* in_sizes, int n_in,
                              void* d_out, int out_size)
{
    const float* x     = (const float*)d_in[0];
    const float* Wq    = (const float*)d_in[1];
    const float* Wk    = (const float*)d_in[2];
    const float* Wv    = (const float*)d_in[3];
    const float* Wo    = (const float*)d_in[4];
    const float* cqw   = (const float*)d_in[5];
    const float* cqb   = (const float*)d_in[6];
    const float* ckw   = (const float*)d_in[7];
    const float* ckb   = (const float*)d_in[8];
    const float* slope = (const float*)d_in[9];
    float* out = (float*)d_out;

    static cudaStream_t s2 = nullptr;
    static cudaEvent_t evF, ev1, evWo, evG, evK, evV, evP, evSC, evO1;
    if (!s2) {
        cudaStreamCreateWithFlags(&s2, cudaStreamNonBlocking);
        cudaEventCreateWithFlags(&evF,  cudaEventDisableTiming);
        cudaEventCreateWithFlags(&ev1,  cudaEventDisableTiming);
        cudaEventCreateWithFlags(&evWo, cudaEventDisableTiming);
        cudaEventCreateWithFlags(&evG,  cudaEventDisableTiming);
        cudaEventCreateWithFlags(&evK,  cudaEventDisableTiming);
        cudaEventCreateWithFlags(&evV,  cudaEventDisableTiming);
        cudaEventCreateWithFlags(&evP,  cudaEventDisableTiming);
        cudaEventCreateWithFlags(&evSC, cudaEventDisableTiming);
        cudaEventCreateWithFlags(&evO1, cudaEventDisableTiming);
    }

    float *qkvpre, *kf, *kT;
    __half *xh, *xl, *wqkvh, *woh, *oh, *ol, *qh, *ql, *kh, *vth, *vtl;
    cudaGetSymbolAddress((void**)&qkvpre, g_qkvpre);
    cudaGetSymbolAddress((void**)&kf,     g_kf);
    cudaGetSymbolAddress((void**)&kT,     g_kT);
    cudaGetSymbolAddress((void**)&xh,     g_xh);
    cudaGetSymbolAddress((void**)&xl,     g_xl);
    cudaGetSymbolAddress((void**)&wqkvh,  g_wqkvh);
    cudaGetSymbolAddress((void**)&woh,    g_woh);
    cudaGetSymbolAddress((void**)&oh,     g_oh);
    cudaGetSymbolAddress((void**)&ol,     g_ol);
    cudaGetSymbolAddress((void**)&qh,     g_qh);
    cudaGetSymbolAddress((void**)&ql,     g_ql);
    cudaGetSymbolAddress((void**)&kh,     g_kh);
    cudaGetSymbolAddress((void**)&vth,    g_vTh);
    cudaGetSymbolAddress((void**)&vtl,    g_vTl);

    cudaFuncSetAttribute(hgemm2,    cudaFuncAttributeMaxDynamicSharedMemorySize, G2_SMEM);
    cudaFuncSetAttribute(kvloc_mma, cudaFuncAttributeMaxDynamicSharedMemorySize, HG_SMEM);
    cudaFuncSetAttribute(sc_mma,    cudaFuncAttributeMaxDynamicSharedMemorySize, HG_SMEM);
    cudaFuncSetAttribute(out_mma,   cudaFuncAttributeMaxDynamicSharedMemorySize, HG_SMEM);

    const int M = Bb * Ls;   // 4096

    // ---- fork: weight preparation on side stream ----
    cudaEventRecord(evF, 0);
    cudaStreamWaitEvent(s2, evF, 0);
    tsplit<<<dim3(HD / 32, HIDd / 32), 256, 0, s2>>>(Wq, wqkvh, HIDd, HD);
    tsplit<<<dim3(KD / 32, HIDd / 32), 256, 0, s2>>>(Wk, wqkvh + (size_t)HD * HIDd, HIDd, KD);
    tsplit<<<dim3(KD / 32, HIDd / 32), 256, 0, s2>>>(Wv, wqkvh + (size_t)(HD + KD) * HIDd, HIDd, KD);
    cudaEventRecord(ev1, s2);
    tsplit<<<dim3(HIDd / 32, HD / 32), 256, 0, s2>>>(Wo, woh, HD, HIDd);
    cudaEventRecord(evWo, s2);

    // ---- main: x split + fused QKV projection ----
    convsplit<<<(M * HIDd / 4 + 255) / 256, 256>>>(x, xh, xl, M * HIDd / 4);
    cudaStreamWaitEvent(0, ev1, 0);
    hgemm2<<<dim3(NQKV / 256, M / 128), 256, G2_SMEM>>>(xh, xl, wqkvh, qkvpre, M, HIDd, NQKV);
    cudaEventRecord(evG, 0);

    // ---- side stream: k path (conv_k -> kT) ----
    cudaStreamWaitEvent(s2, evG, 0);
    conv_silu_split<<<(M * KD / 2 + 255) / 256, 256, 0, s2>>>(qkvpre + HD, NQKV, ckw, ckb, kh, nullptr, kf, KD, M * KD / 2);
    cudaEventRecord(evK, s2);
    trans_f32<<<dim3(Ls / 32, Dd / 32, 16), 256, 0, s2>>>(kf, kT);

    // ---- main: v transpose + conv_q ----
    trans_split<<<dim3(Ls / 32, Dd / 32, 16), 256>>>(qkvpre, NQKV, HD + KD, vth, vtl);
    cudaEventRecord(evV, 0);
    conv_silu_split<<<(M * HD / 2 + 255) / 256, 256>>>(qkvpre, NQKV, cqw, cqb, qh, ql, nullptr, HD, M * HD / 2);

    // ---- side stream: kvloc + prefix (needs vT from main) ----
    cudaStreamWaitEvent(s2, evV, 0);
    kvloc_mma<<<dim3(2, 2, Bb * Hh * NB), 256, HG_SMEM, s2>>>(slope);
    kvprefix_split<<<(Bb * Hh * 32768) / 256, 256, 0, s2>>>(slope);
    cudaEventRecord(evP, s2);

    // ---- main: sc (needs k from side stream) ----
    cudaStreamWaitEvent(0, evK, 0);
    sc_mma<<<dim3(2, 2, Bb * Hh * NB), 256, HG_SMEM>>>(slope);
    cudaEventRecord(evSC, 0);

    // ---- side stream: out for b=1 (needs sc + kv chain) ----
    cudaStreamWaitEvent(s2, evSC, 0);
    out_mma<<<dim3(2, 2, Hh * NB), 256, HG_SMEM, s2>>>(slope, Hh * NB);
    cudaEventRecord(evO1, s2);

    // ---- main: out b=0 -> rms b=0 -> Wo b=0 (overlaps out b=1 on s2) ----
    cudaStreamWaitEvent(0, evP, 0);
    out_mma<<<dim3(2, 2, Hh * NB), 256, HG_SMEM>>>(slope, 0);
    rmsnorm_split_kernel<<<M / 2, 256>>>(0);
    cudaStreamWaitEvent(0, evWo, 0);
    hgemm2<<<dim3(HIDd / 256, (M / 2) / 128), 256, G2_SMEM>>>(oh, ol, woh, out, M / 2, HD, HIDd);

    // ---- main: join b=1, finish rms + Wo ----
    cudaStreamWaitEvent(0, evO1, 0);
    rmsnorm_split_kernel<<<M / 2, 256>>>(M / 2);
    hgemm2<<<dim3(HIDd / 256, (M / 2) / 128), 256, G2_SMEM>>>(
        oh + (size_t)(M / 2) * HD, ol + (size_t)(M / 2) * HD, woh,
        out + (size_t)(M / 2) * HIDd, M / 2, HD, HIDd);
}